// round 11
// baseline (speedup 1.0000x reference)
#include <cuda_runtime.h>
#include <cstdint>

#define V 8192
#define NB 64
#define M3 24576
#define STRIDE 8194
#define MT 128
#define NTILE 192            // 24576 / 128 m-tiles
#define KS 16                // split-K factor -> 512 K per unit
#define NUNITS (NTILE * KS)  // 3072
#define GRID 296             // persistent, 2 CTAs/SM
#define KC 32
#define SPU 16               // stages per unit (512/32)
#define NST 4                // cp.async ring depth (lookahead 3)

#define PC 132               // C tile pitch (floats)
#define PFW 72               // f pair-tile pitch (words)
#define PD 72

#define CS_FLOATS (KC * PC)                  // 4224
#define FS_WORDS  (16 * PFW)                 // 1152
#define SB_FLOATS (CS_FLOATS + FS_WORDS)     // 5376
#define SB_BYTES  (SB_FLOATS * 4)            // 21504
#define DS_OFF    (NST * SB_FLOATS)          // 21504 floats
#define SOUT_OFF  (DS_OFF + 64 * PD)         // 26112
#define SMEM_DYN  ((SOUT_OFF + 192) * 4)     // 105216 B -> 2 CTAs/SM (210KB/SM)

#define MMA_BF16(d, a0, a1, a2, a3, b0, b1)                                   \
    asm volatile("mma.sync.aligned.m16n8k16.row.col.f32.bf16.bf16.f32 "       \
        "{%0,%1,%2,%3}, {%4,%5,%6,%7}, {%8,%9}, {%0,%1,%2,%3};"               \
        : "+f"((d)[0]), "+f"((d)[1]), "+f"((d)[2]), "+f"((d)[3])              \
        : "r"(a0), "r"(a1), "r"(a2), "r"(a3), "r"(b0), "r"(b1))

#define CP16(dst_u32, src_gl) \
    asm volatile("cp.async.cg.shared.global [%0], [%1], 16;" :: "r"(dst_u32), "l"(src_gl))
#define CP_COMMIT()  asm volatile("cp.async.commit_group;" ::: "memory")
#define CP_WAIT2()   asm volatile("cp.async.wait_group 2;" ::: "memory")

// f packed as bf16 k-pairs: g_fP[i2*64 + b] = {lo: f[b][2*i2], hi: f[b][2*i2+1]}
__device__ unsigned g_fP[(V / 2) * NB];   // 1 MB, L2-resident

__device__ __forceinline__ unsigned pack_bf16(float lo, float hi) {
    unsigned r;
    asm("cvt.rn.bf16x2.f32 %0, %1, %2;" : "=r"(r) : "f"(hi), "f"(lo));
    return r;
}

// ---------------------------------------------------------------------------
__global__ void prep_kernel(const float* __restrict__ func, float* __restrict__ out) {
    int idx = blockIdx.x * 256 + threadIdx.x;    // < (V/2)*NB = 262144
    int i2 = idx >> 6;
    int b  = idx & 63;
    float lo = func[b * STRIDE + 2 * i2];
    float hi = func[b * STRIDE + 2 * i2 + 1];
    g_fP[idx] = pack_bf16(lo, hi);
    if (idx < NB) {
        const float QI = 1000000000.0f;
        float a1 = func[idx * STRIDE + V];
        float a2 = func[idx * STRIDE + V + 1];
        out[idx * 3 + 0] = a1 * -QI;
        out[idx * 3 + 1] = (1.0f - (1.0f - a1) * (1.0f - a2)) * -QI;
        out[idx * 3 + 2] = 0.0f;
    }
}

// ---------------------------------------------------------------------------
// Persistent bf16 mma.sync GEMM, 2 CTAs/SM, 4-deep cp.async ring (3 ahead).
// ---------------------------------------------------------------------------
__global__ __launch_bounds__(256, 2)
void cooc_mma(const float* __restrict__ cooc,
              const float* __restrict__ arg,
              float* __restrict__ out) {
    extern __shared__ float sm[];
    float* Ds   = sm + DS_OFF;
    float* sout = sm + SOUT_OFF;

    const int tid  = threadIdx.x;
    const int lane = tid & 31;
    const int wid  = tid >> 5;
    const int mg   = wid & 3;
    const int kg   = wid >> 2;
    const int quad = lane & 3;
    const int qid  = lane >> 2;
    const int bid  = blockIdx.x;

    const int nu    = 1 + (NUNITS - 1 - bid) / GRID;
    const int total = nu * SPU;

    unsigned smem_base;
    asm("{ .reg .u64 t; cvta.to.shared.u64 t, %1; cvt.u32.u64 %0, t; }"
        : "=r"(smem_base) : "l"(sm));

    int crow[4], cc16[4];
    #pragma unroll
    for (int it = 0; it < 4; it++) {
        int flat = it * 256 + tid;
        crow[it] = flat >> 5;
        cc16[it] = flat & 31;
    }
    const int f_row = tid >> 4;     // 0..15 (k2 rows)
    const int f_c16 = tid & 15;

    const char* cooc_g = (const char*)__cvta_generic_to_global(cooc);
    const char* fP_g   = (const char*)__cvta_generic_to_global(g_fP);

    // -------- incremental issue-stream state ----
    int u_i  = bid;
    int sl_i = 0;
    int m0_i, k0_i;
    {
        int ks = u_i / NTILE;
        m0_i = (u_i - ks * NTILE) * MT;
        k0_i = ks * (V / KS);
    }
    int slot_i = 0;

    auto issue = [&]() {
        unsigned buf = smem_base + (unsigned)(slot_i * SB_BYTES);
        #pragma unroll
        for (int it = 0; it < 4; it++) {
            const char* src = cooc_g + ((size_t)(k0_i + crow[it]) * M3 + m0_i + cc16[it] * 4) * 4;
            CP16(buf + (unsigned)(crow[it] * PC + cc16[it] * 4) * 4, src);
        }
        unsigned fb = buf + CS_FLOATS * 4;
        const char* fsrc = fP_g + ((size_t)((k0_i >> 1) + f_row) * 64 + f_c16 * 4) * 4;
        CP16(fb + (unsigned)(f_row * PFW + f_c16 * 4) * 4, fsrc);
    };
    auto adv = [&]() {
        slot_i = (slot_i == NST - 1) ? 0 : slot_i + 1;
        if (++sl_i == SPU) {
            sl_i = 0;
            u_i += GRID;
            if (u_i < NUNITS) {
                int ks = u_i / NTILE;
                m0_i = (u_i - ks * NTILE) * MT;
                k0_i = ks * (V / KS);
            }
        } else {
            k0_i += KC;
        }
    };

    float acc[2][8][4];
    #pragma unroll
    for (int mt = 0; mt < 2; mt++)
        #pragma unroll
        for (int nt = 0; nt < 8; nt++)
            #pragma unroll
            for (int r = 0; r < 4; r++) acc[mt][nt][r] = 0.0f;

    float po0 = 0.f, po1 = 0.f, po2 = 0.f;
    const int bb = tid & 63;
    const int mq = tid >> 6;
    const float* argb = arg + bb * STRIDE;

    int u_c  = bid;
    int m0_c;
    {
        int ks = u_c / NTILE;
        m0_c = (u_c - ks * NTILE) * MT;
    }

    // prologue: 3 stages in flight
    issue(); CP_COMMIT(); adv();
    issue(); CP_COMMIT(); adv();
    issue(); CP_COMMIT(); adv();

    int slot_c = 0;

    for (int g = 0; g < total; g++) {
        CP_WAIT2();                        // group g complete (<=2 pending)
        __syncthreads();                   // all warps done with compute(g-1); data visible

        if (g + 3 < total) issue();        // slot (g+3)&3 == (g-1)&3, safe post-sync
        CP_COMMIT();
        adv();

        // ---- compute stage g ----
        const float* buf = sm + slot_c * SB_FLOATS;
        slot_c = (slot_c == NST - 1) ? 0 : slot_c + 1;

        const float* ca = buf + (kg * 16 + 2 * quad) * PC + mg * 32 + qid;
        const unsigned* fb = (const unsigned*)(buf + CS_FLOATS) + (kg * 8 + quad) * PFW + qid;

        unsigned b0[8], b1[8];
        #pragma unroll
        for (int nt = 0; nt < 8; nt++) {
            b0[nt] = fb[nt * 8];
            b1[nt] = fb[4 * PFW + nt * 8];
        }

        #pragma unroll
        for (int mt = 0; mt < 2; mt++) {
            const float* cm = ca + mt * 16;
            unsigned a0 = pack_bf16(cm[0],          cm[PC]);
            unsigned a1 = pack_bf16(cm[8],          cm[PC + 8]);
            unsigned a2 = pack_bf16(cm[8 * PC],     cm[9 * PC]);
            unsigned a3 = pack_bf16(cm[8 * PC + 8], cm[9 * PC + 8]);
            #pragma unroll
            for (int nt = 0; nt < 8; nt++)
                MMA_BF16(acc[mt][nt], a0, a1, a2, a3, b0[nt], b1[nt]);
        }

        // ---- unit boundary: two-pass fold + reduce ----
        if ((g & (SPU - 1)) == SPU - 1) {
            #pragma unroll
            for (int p = 0; p < 2; p++) {
                __syncthreads();
                if (kg == 0) {
                    int cr = mg * 16 + qid;
                    #pragma unroll
                    for (int nt = 0; nt < 8; nt++) {
                        int bc = nt * 8 + 2 * quad;
                        Ds[cr * PD + bc]           = acc[p][nt][0];
                        Ds[cr * PD + bc + 1]       = acc[p][nt][1];
                        Ds[(cr + 8) * PD + bc]     = acc[p][nt][2];
                        Ds[(cr + 8) * PD + bc + 1] = acc[p][nt][3];
                    }
                }
                __syncthreads();
                if (kg == 1) {
                    int cr = mg * 16 + qid;
                    #pragma unroll
                    for (int nt = 0; nt < 8; nt++) {
                        int bc = nt * 8 + 2 * quad;
                        Ds[cr * PD + bc]           += acc[p][nt][0];
                        Ds[cr * PD + bc + 1]       += acc[p][nt][1];
                        Ds[(cr + 8) * PD + bc]     += acc[p][nt][2];
                        Ds[(cr + 8) * PD + bc + 1] += acc[p][nt][3];
                    }
                }
                __syncthreads();
                #pragma unroll 4
                for (int mm = 0; mm < 16; mm++) {
                    int m = m0_c + mq * 32 + p * 16 + mm;
                    unsigned j = (unsigned)m / 3u;
                    int k = m - 3 * (int)j;
                    float t = Ds[(mq * 16 + mm) * PD + bb] * __ldg(argb + j);
                    if (k == 0) po0 += t;
                    else if (k == 1) po1 += t;
                    else po2 += t;
                }
            }
            __syncthreads();

            #pragma unroll
            for (int mt = 0; mt < 2; mt++)
                #pragma unroll
                for (int nt = 0; nt < 8; nt++)
                    #pragma unroll
                    for (int r = 0; r < 4; r++) acc[mt][nt][r] = 0.0f;

            u_c += GRID;
            if (u_c < NUNITS) {
                int ks = u_c / NTILE;
                m0_c = (u_c - ks * NTILE) * MT;
            }
        }
    }

    // ---- final flush ----
    if (tid < 192) sout[tid] = 0.0f;
    __syncthreads();
    atomicAdd(&sout[bb * 3 + 0], po0);
    atomicAdd(&sout[bb * 3 + 1], po1);
    atomicAdd(&sout[bb * 3 + 2], po2);
    __syncthreads();
    if (tid < 192) atomicAdd(&out[tid], sout[tid]);
}

// ---------------------------------------------------------------------------
extern "C" void kernel_launch(void* const* d_in, const int* in_sizes, int n_in,
                              void* d_out, int out_size) {
    const float* func = (const float*)d_in[0];
    const float* arg  = (const float*)d_in[1];
    const float* cooc = (const float*)d_in[2];
    float* out = (float*)d_out;

    cudaFuncSetAttribute(cooc_mma, cudaFuncAttributeMaxDynamicSharedMemorySize, SMEM_DYN);

    prep_kernel<<<((V / 2) * NB) / 256, 256>>>(func, out);
    cooc_mma<<<GRID, 256, SMEM_DYN>>>(cooc, arg, out);
}